// round 14
// baseline (speedup 1.0000x reference)
#include <cuda_runtime.h>
#include <math.h>

#define T_STEPS 1024
#define K_FEAT  512
#define BLOCK   64
#define PF      52   // prefetch ring depth, just under ~55 outstanding-LDG/warp cap
#define PFD     16   // extra L2-prefetch lead distance (steps beyond the ring frontier)

// One thread owns one (batch, feature) pair; serial 2-state affine scan over
// T=1024. R12 base (best: 41.9us kernel, DRAM 65.8%, __stwt stores) plus ONE
// change: per-step prefetch.global.L2 targeting t+PF+PFD. The L1tex wavefront
// queue holds each LDG for its full latency; turning DRAM-latency LDGs into
// L2-hit LDGs (~600 -> ~240 cyc residency) raises queue turnover ~2.5x
// without more warps/registers. Prefetches are fire-and-forget: no queue
// slot, no writeback. Max prefetch target = step 1003 < 1024, so the 18 full
// chunks need no bounds guard; partial chunk/epilogue issue none.
__global__ void __launch_bounds__(BLOCK) alpha_filter_kernel(
    const float* __restrict__ in,     // [B, T, K]
    const float* __restrict__ init,   // [K]
    const float* __restrict__ tau,    // [K]
    float* __restrict__ out)          // [B, T, K]
{
    const int k = blockIdx.x * BLOCK + threadIdx.x;
    const int b = blockIdx.y;

    // Per-feature coefficients (matches reference fp32 math)
    const float tc      = fmaxf(tau[k], 1e-8f);
    const float dt_tau  = 0.001f / tc;
    const float dt_tau2 = dt_tau / tc;
    const float e       = expf(-dt_tau);

    const float a00 = e * (1.0f - dt_tau);
    const float a01 = -e * dt_tau2;
    const float a10 = e * 0.001f;
    const float a11 = e * (1.0f + dt_tau);
    const float b0  = e * dt_tau2;
    const float b1  = 1.0f - a11;

    float x0 = 0.0f;
    float x1 = init[k];

    const size_t base = (size_t)b * T_STEPS * K_FEAT + (size_t)k;
    const float* ip = in  + base;
    float*       op = out + base;

    // Prologue: fill the prefetch ring with t = 0..PF-1
    float buf[PF];
#pragma unroll
    for (int i = 0; i < PF; ++i)
        buf[i] = ip[(size_t)i * K_FEAT];
    ip += (size_t)PF * K_FEAT;

    // Main loop: consume step t, LDG-prefetch step t+PF, L2-prefetch t+PF+PFD.
    // Steps that still prefetch = T_STEPS - PF = 972: 18 full chunks of 52
    // plus a partial chunk of 36.
#pragma unroll 1
    for (int done = 0; done + PF <= T_STEPS - PF; done += PF) {
#pragma unroll
        for (int i = 0; i < PF; ++i) {
            const float u = buf[i];
            buf[i] = ip[(size_t)i * K_FEAT];   // ring load: step t + PF
            // L2 prefetch: step t + PF + PFD (in-bounds for all full chunks)
            asm volatile("prefetch.global.L2 [%0];"
                         :: "l"(ip + (size_t)(i + PFD) * K_FEAT));
            const float nx0 = fmaf(a00, x0, fmaf(a01, x1, b0 * u));
            const float nx1 = fmaf(a10, x0, fmaf(a11, x1, b1 * u));
            x0 = nx0;
            x1 = nx1;
            __stwt(op + (size_t)i * K_FEAT, nx1);
        }
        ip += (size_t)PF * K_FEAT;
        op += (size_t)PF * K_FEAT;
    }

    // Partial chunk: remaining steps that still ring-load (no L2 prefetch —
    // targets would run past the end of this batch row).
#define REM ((T_STEPS - PF) % PF)
#if REM
#pragma unroll
    for (int i = 0; i < REM; ++i) {
        const float u = buf[i];
        buf[i] = ip[(size_t)i * K_FEAT];
        const float nx0 = fmaf(a00, x0, fmaf(a01, x1, b0 * u));
        const float nx1 = fmaf(a10, x0, fmaf(a11, x1, b1 * u));
        x0 = nx0;
        x1 = nx1;
        __stwt(op + (size_t)i * K_FEAT, nx1);
    }
    ip += (size_t)REM * K_FEAT;
    op += (size_t)REM * K_FEAT;
#endif

    // Epilogue: drain the last PF buffered inputs (no further loads).
    // Ring read order continues from index REM (mod PF).
#pragma unroll
    for (int i = 0; i < PF; ++i) {
        const int idx = (REM + i) % PF;
        const float u = buf[idx];
        const float nx0 = fmaf(a00, x0, fmaf(a01, x1, b0 * u));
        const float nx1 = fmaf(a10, x0, fmaf(a11, x1, b1 * u));
        x0 = nx0;
        x1 = nx1;
        __stwt(op + (size_t)i * K_FEAT, nx1);
    }
}

extern "C" void kernel_launch(void* const* d_in, const int* in_sizes, int n_in,
                              void* d_out, int out_size) {
    const float* inputs = (const float*)d_in[0];   // [B, T, K]
    const float* init   = (const float*)d_in[1];   // [K]
    const float* tau    = (const float*)d_in[2];   // [K]
    float*       out    = (float*)d_out;

    const int batch = in_sizes[0] / (T_STEPS * K_FEAT);   // 64
    dim3 grid(K_FEAT / BLOCK, batch);
    alpha_filter_kernel<<<grid, BLOCK>>>(inputs, init, tau, out);
}

// round 15
// speedup vs baseline: 1.0409x; 1.0409x over previous
#include <cuda_runtime.h>
#include <math.h>

#define T_STEPS 1024
#define K_FEAT  512
#define BLOCK   64
#define PF      64   // ring depth; T-PF = 960 = 15*64 exactly (no modular epilogue)

// One thread owns one (batch, feature) pair; serial 2-state affine scan over
// T=1024. R12 base (best: 41.9us kernel, DRAM 65.8%; __stwt stores, default
// loads) with ONE change: PF 52 -> 64. Ring divides T exactly so the partial
// chunk and the %PF epilogue indexing vanish. regs ~140 (no spill; grid-
// limited occupancy makes the register budget free).
// Mapped and falsified this session: load policies (ldcg/ldcs worse),
// store policies (wt > cs > plain), cp.async staging, L2 prefetch, vector
// widths (warp count dominates; 1024 warps is structural max), wave balance.
__global__ void __launch_bounds__(BLOCK) alpha_filter_kernel(
    const float* __restrict__ in,     // [B, T, K]
    const float* __restrict__ init,   // [K]
    const float* __restrict__ tau,    // [K]
    float* __restrict__ out)          // [B, T, K]
{
    const int k = blockIdx.x * BLOCK + threadIdx.x;
    const int b = blockIdx.y;

    // Per-feature coefficients (matches reference fp32 math)
    const float tc      = fmaxf(tau[k], 1e-8f);
    const float dt_tau  = 0.001f / tc;
    const float dt_tau2 = dt_tau / tc;
    const float e       = expf(-dt_tau);

    const float a00 = e * (1.0f - dt_tau);
    const float a01 = -e * dt_tau2;
    const float a10 = e * 0.001f;
    const float a11 = e * (1.0f + dt_tau);
    const float b0  = e * dt_tau2;
    const float b1  = 1.0f - a11;

    float x0 = 0.0f;
    float x1 = init[k];

    const size_t base = (size_t)b * T_STEPS * K_FEAT + (size_t)k;
    const float* ip = in  + base;
    float*       op = out + base;

    // Prologue: fill the prefetch ring with t = 0..PF-1
    float buf[PF];
#pragma unroll
    for (int i = 0; i < PF; ++i)
        buf[i] = ip[(size_t)i * K_FEAT];
    ip += (size_t)PF * K_FEAT;

    // Main loop: consume step t, ring-load step t+PF.
    // Steps that still load = T_STEPS - PF = 960 = 15 chunks of 64.
#pragma unroll 1
    for (int blk = 0; blk < (T_STEPS - PF) / PF; ++blk) {
#pragma unroll
        for (int i = 0; i < PF; ++i) {
            const float u = buf[i];
            buf[i] = ip[(size_t)i * K_FEAT];   // ring load: step t + PF
            const float nx0 = fmaf(a00, x0, fmaf(a01, x1, b0 * u));
            const float nx1 = fmaf(a10, x0, fmaf(a11, x1, b1 * u));
            x0 = nx0;
            x1 = nx1;
            __stwt(op + (size_t)i * K_FEAT, nx1);
        }
        ip += (size_t)PF * K_FEAT;
        op += (size_t)PF * K_FEAT;
    }

    // Epilogue: drain the last PF buffered inputs (no further loads;
    // ring index starts at 0 because PF divides T exactly).
#pragma unroll
    for (int i = 0; i < PF; ++i) {
        const float u = buf[i];
        const float nx0 = fmaf(a00, x0, fmaf(a01, x1, b0 * u));
        const float nx1 = fmaf(a10, x0, fmaf(a11, x1, b1 * u));
        x0 = nx0;
        x1 = nx1;
        __stwt(op + (size_t)i * K_FEAT, nx1);
    }
}

extern "C" void kernel_launch(void* const* d_in, const int* in_sizes, int n_in,
                              void* d_out, int out_size) {
    const float* inputs = (const float*)d_in[0];   // [B, T, K]
    const float* init   = (const float*)d_in[1];   // [K]
    const float* tau    = (const float*)d_in[2];   // [K]
    float*       out    = (float*)d_out;

    const int batch = in_sizes[0] / (T_STEPS * K_FEAT);   // 64
    dim3 grid(K_FEAT / BLOCK, batch);
    alpha_filter_kernel<<<grid, BLOCK>>>(inputs, init, tau, out);
}